// round 4
// baseline (speedup 1.0000x reference)
#include <cuda_runtime.h>

// Problem constants
#define BP   128          // B*P
#define SEQ  1024         // S
#define DIM  1024         // D
#define NH   16           // heads
#define DH   64           // depth per head
#define SCALE 0.125f      // 1/sqrt(64)
#define SIGMA 0.1f

// ---------------- scratch (device globals; no allocation allowed) ------------
__device__ float g_qp[BP * DIM];
__device__ float g_kp[BP * DIM];
__device__ float g_vp[BP * DIM];
__device__ float g_part[BP * 32 * DIM];   // [bp][chunk][dim] normalized partials
__device__ float g_zsum[32 * BP * NH];    // per-s-chunk exp sums
__device__ float g_zh[BP * DIM];          // merged attention output (mean_z)

// ---------------- projection GEMM -------------------------------------------
// out[m][n] = x[m][:]·W[:][n] + b[n] + SIGMA*nz[m][n]
// Block: 128 rows x 16 cols, 256 threads, micro-tile 2x4. 64 blocks per matrix.
__device__ __forceinline__ void proj_body(const float* __restrict__ x,
                                          const float* __restrict__ W,
                                          const float* __restrict__ bias,
                                          const float* __restrict__ nz,
                                          float* __restrict__ out,
                                          int colBase)
{
    __shared__ float xs[32][132];   // [k][m], padded
    __shared__ float ws[32][16];    // [k][n]

    const int tid = threadIdx.x;          // 0..255
    const int tx  = tid & 3;              // 4 col-groups of 4
    const int ty  = tid >> 2;             // 64 row-groups of 2

    float acc[2][4];
#pragma unroll
    for (int i = 0; i < 2; i++)
#pragma unroll
        for (int j = 0; j < 4; j++) acc[i][j] = 0.f;

    for (int kk = 0; kk < DIM; kk += 32) {
        // x tile: 128 rows x 32 k = 1024 float4 / 256 threads = 4 each
#pragma unroll
        for (int r = 0; r < 4; r++) {
            int i  = tid + r * 256;
            int m  = i >> 3;
            int kq = (i & 7) << 2;
            float4 v = *reinterpret_cast<const float4*>(x + m * DIM + kk + kq);
            xs[kq + 0][m] = v.x;
            xs[kq + 1][m] = v.y;
            xs[kq + 2][m] = v.z;
            xs[kq + 3][m] = v.w;
        }
        // W tile: 32 k x 16 n = 128 float4; threads < 128
        if (tid < 128) {
            int k  = tid >> 2;
            int nq = (tid & 3) << 2;
            *reinterpret_cast<float4*>(&ws[k][nq]) =
                *reinterpret_cast<const float4*>(W + (kk + k) * DIM + colBase + nq);
        }
        __syncthreads();

#pragma unroll 8
        for (int k = 0; k < 32; k++) {
            float2 a = *reinterpret_cast<const float2*>(&xs[k][ty << 1]);
            float4 b = *reinterpret_cast<const float4*>(&ws[k][tx << 2]);
            acc[0][0] += a.x * b.x; acc[0][1] += a.x * b.y;
            acc[0][2] += a.x * b.z; acc[0][3] += a.x * b.w;
            acc[1][0] += a.y * b.x; acc[1][1] += a.y * b.y;
            acc[1][2] += a.y * b.z; acc[1][3] += a.y * b.w;
        }
        __syncthreads();
    }

    int n0 = colBase + (tx << 2);
    float4 bb = *reinterpret_cast<const float4*>(bias + n0);
#pragma unroll
    for (int i = 0; i < 2; i++) {
        int m = (ty << 1) + i;
        float4 nn = *reinterpret_cast<const float4*>(nz + m * DIM + n0);
        float4 r;
        r.x = acc[i][0] + bb.x + SIGMA * nn.x;
        r.y = acc[i][1] + bb.y + SIGMA * nn.y;
        r.z = acc[i][2] + bb.z + SIGMA * nn.z;
        r.w = acc[i][3] + bb.w + SIGMA * nn.w;
        *reinterpret_cast<float4*>(out + m * DIM + n0) = r;
    }
}

__global__ void __launch_bounds__(256)
proj3_kernel(const float* __restrict__ q, const float* __restrict__ k,
             const float* __restrict__ v,
             const float* __restrict__ Wq, const float* __restrict__ Wk,
             const float* __restrict__ Wv,
             const float* __restrict__ bq, const float* __restrict__ bk,
             const float* __restrict__ bv,
             const float* __restrict__ nq, const float* __restrict__ nk,
             const float* __restrict__ nv)
{
    int mat = blockIdx.y;
    const float* x = (mat == 0) ? q  : (mat == 1) ? k  : v;
    const float* W = (mat == 0) ? Wq : (mat == 1) ? Wk : Wv;
    const float* b = (mat == 0) ? bq : (mat == 1) ? bk : bv;
    const float* n = (mat == 0) ? nq : (mat == 1) ? nk : nv;
    float* o       = (mat == 0) ? g_qp : (mat == 1) ? g_kp : g_vp;
    proj_body(x, W, b, n, o, blockIdx.x * 16);
}

__global__ void __launch_bounds__(256)
projZ_kernel(const float* __restrict__ Wz, const float* __restrict__ bz,
             const float* __restrict__ nz, float* __restrict__ z_out)
{
    proj_body(g_zh, Wz, bz, nz, z_out, blockIdx.x * 16);
}

// ---------------- copy K -> K_out (slot write) + logits + chunk exp-sums ----
// grid (32 s-chunks, 128 bp), 256 threads. Thread t handles cols 4t..4t+3.
// Head logit reduced across 16-lane groups via shuffles.
__global__ void __launch_bounds__(256)
copyK_kernel(const float* __restrict__ K, float* __restrict__ Kout,
             float* __restrict__ logits, const int* __restrict__ tptr)
{
    const int bp  = blockIdx.y;
    const int s0  = blockIdx.x * 32;
    const int tid = threadIdx.x;
    const int lane = tid & 31;
    const int t   = *tptr;

    __shared__ float we[32][NH + 1];   // exp(logit) per s-row, per head

    float4 q4 = *reinterpret_cast<const float4*>(g_qp + bp * DIM + (tid << 2));
    const float* kprow = g_kp + bp * DIM;
    const float* Kb  = K    + (size_t)bp * SEQ * DIM;
    float*       Ob  = Kout + (size_t)bp * SEQ * DIM;
    const int h = tid >> 4;            // head owning these 4 cols

    for (int slb = 0; slb < 32; slb += 4) {
        float4 vv[4];
#pragma unroll
        for (int j = 0; j < 4; j++) {
            int s = s0 + slb + j;
            const float* src = Kb + (size_t)s * DIM + (tid << 2);
            vv[j] = (s == t) ? *reinterpret_cast<const float4*>(kprow + (tid << 2))
                             : __ldcs(reinterpret_cast<const float4*>(src));
        }
#pragma unroll
        for (int j = 0; j < 4; j++) {
            int s = s0 + slb + j;
            __stcs(reinterpret_cast<float4*>(Ob + (size_t)s * DIM + (tid << 2)), vv[j]);
            float p = vv[j].x * q4.x + vv[j].y * q4.y + vv[j].z * q4.z + vv[j].w * q4.w;
#pragma unroll
            for (int o = 8; o > 0; o >>= 1)
                p += __shfl_xor_sync(0xffffffffu, p, o);
            if ((lane & 15) == 0) {
                float l = p * SCALE;
                logits[((size_t)(bp * NH + h)) * SEQ + s] = l;
                we[slb + j][h] = __expf(l);
            }
        }
    }
    __syncthreads();

    if (tid < NH) {
        float z = 0.f;
#pragma unroll
        for (int sl = 0; sl < 32; sl++) z += we[sl][tid];
        g_zsum[((size_t)blockIdx.x * BP + bp) * NH + tid] = z;
    }
}

// ---------------- copy V -> V_out (slot write) + normalized attn + partials -
// Reads logits for its chunk, normalizes with the GLOBAL exp-sum (all copyK
// chunks are done), writes softmaxed attn in place, accumulates normalized
// attn·V partials. Eliminates the separate softmax kernel.
__global__ void __launch_bounds__(256)
copyV_kernel(const float* __restrict__ V, float* __restrict__ Vout,
             float* __restrict__ attn, const int* __restrict__ tptr)
{
    const int bp  = blockIdx.y;
    const int s0  = blockIdx.x * 32;
    const int tid = threadIdx.x;
    const int t   = *tptr;

    __shared__ float zinv[NH];
    __shared__ float wa[32][NH + 1];

    if (tid < NH) {
        float z = 0.f;
#pragma unroll
        for (int c = 0; c < 32; c++) z += g_zsum[((size_t)c * BP + bp) * NH + tid];
        zinv[tid] = 1.f / z;
    }
    __syncthreads();

    // normalized weights for this chunk; also write softmaxed attn output
#pragma unroll
    for (int r = 0; r < 2; r++) {
        int i  = tid + r * 256;            // 0..511
        int sl = i >> 4;
        int h  = i & 15;
        size_t idx = ((size_t)(bp * NH + h)) * SEQ + s0 + sl;
        float w = __expf(attn[idx]) * zinv[h];
        wa[sl][h] = w;
        attn[idx] = w;
    }
    __syncthreads();

    const float* vprow = g_vp + bp * DIM;
    const float* Vb  = V    + (size_t)bp * SEQ * DIM;
    float*       Ob  = Vout + (size_t)bp * SEQ * DIM;
    const int h = tid >> 4;
    float4 acc = make_float4(0.f, 0.f, 0.f, 0.f);

    for (int slb = 0; slb < 32; slb += 4) {
        float4 vv[4];
#pragma unroll
        for (int j = 0; j < 4; j++) {
            int s = s0 + slb + j;
            const float* src = Vb + (size_t)s * DIM + (tid << 2);
            vv[j] = (s == t) ? *reinterpret_cast<const float4*>(vprow + (tid << 2))
                             : __ldcs(reinterpret_cast<const float4*>(src));
        }
#pragma unroll
        for (int j = 0; j < 4; j++) {
            int s = s0 + slb + j;
            __stcs(reinterpret_cast<float4*>(Ob + (size_t)s * DIM + (tid << 2)), vv[j]);
            float a = wa[slb + j][h];
            acc.x += a * vv[j].x; acc.y += a * vv[j].y;
            acc.z += a * vv[j].z; acc.w += a * vv[j].w;
        }
    }
    // layout [bp][chunk][dim] so combine streams contiguously
    *reinterpret_cast<float4*>(
        g_part + ((size_t)bp * 32 + blockIdx.x) * DIM + (tid << 2)) = acc;
}

// ---------------- combine: sum 32 chunk partials into g_zh ------------------
__global__ void __launch_bounds__(256)
combine_kernel()
{
    const int bp  = blockIdx.x;
    const int tid = threadIdx.x;            // one float4 column each (256*4 = 1024)
    const float* base = g_part + (size_t)bp * 32 * DIM + (tid << 2);

    float4 acc = make_float4(0.f, 0.f, 0.f, 0.f);
#pragma unroll
    for (int c = 0; c < 32; c++) {
        float4 p = *reinterpret_cast<const float4*>(base + (size_t)c * DIM);
        acc.x += p.x; acc.y += p.y; acc.z += p.z; acc.w += p.w;
    }
    *reinterpret_cast<float4*>(g_zh + (size_t)bp * DIM + (tid << 2)) = acc;
}

// ---------------- launch ----------------------------------------------------
extern "C" void kernel_launch(void* const* d_in, const int* in_sizes, int n_in,
                              void* d_out, int out_size)
{
    const float* q   = (const float*)d_in[0];
    const float* k   = (const float*)d_in[1];
    const float* v   = (const float*)d_in[2];
    const float* Kin = (const float*)d_in[3];
    const float* Vin = (const float*)d_in[4];
    const float* Wq  = (const float*)d_in[5];
    const float* bq  = (const float*)d_in[6];
    const float* Wk  = (const float*)d_in[7];
    const float* bk  = (const float*)d_in[8];
    const float* Wv  = (const float*)d_in[9];
    const float* bv  = (const float*)d_in[10];
    const float* Wz  = (const float*)d_in[11];
    const float* bz  = (const float*)d_in[12];
    const float* nq  = (const float*)d_in[13];
    const float* nk  = (const float*)d_in[14];
    const float* nv  = (const float*)d_in[15];
    const float* nz  = (const float*)d_in[16];
    const int* tstep = (const int*)d_in[17];

    float* out   = (float*)d_out;
    float* z_out = out;                                       // 128*1024
    float* K_out = out + (size_t)BP * DIM;                    // 128*1024*1024
    float* V_out = K_out + (size_t)BP * SEQ * DIM;
    float* attn  = V_out + (size_t)BP * SEQ * DIM;            // 128*16*1024

    // 1. projections q/k/v (+bias +sigma*noise)
    proj3_kernel<<<dim3(64, 3), 256>>>(q, k, v, Wq, Wk, Wv, bq, bk, bv, nq, nk, nv);
    // 2. K copy (slot write) + logits + per-chunk exp sums
    copyK_kernel<<<dim3(32, BP), 256>>>(Kin, K_out, attn, tstep);
    // 3. V copy (slot write) + softmaxed attn written in place + partials
    copyV_kernel<<<dim3(32, BP), 256>>>(Vin, V_out, attn, tstep);
    // 4. sum partials -> zh
    combine_kernel<<<BP, 256>>>();
    // 5. output projection z
    projZ_kernel<<<dim3(64, 1), 256>>>(Wz, bz, nz, z_out);
}

// round 5
// speedup vs baseline: 1.4127x; 1.4127x over previous
#include <cuda_runtime.h>

// Problem constants
#define BP   128          // B*P
#define SEQ  1024         // S
#define DIM  1024         // D
#define NH   16           // heads
#define DH   64           // depth per head
#define SCALE 0.125f      // 1/sqrt(64)
#define SIGMA 0.1f

// ---------------- scratch (device globals; no allocation allowed) ------------
__device__ float g_qp[BP * DIM];
__device__ float g_kp[BP * DIM];
__device__ float g_vp[BP * DIM];
__device__ float g_part[32 * BP * DIM];   // per-s-chunk partial sums of attn·V
__device__ float g_zh[BP * DIM];          // merged attention output (mean_z)

// ---------------- projection GEMM -------------------------------------------
// out[m][n] = x[m][:]·W[:][n] + b[n] + SIGMA*nz[m][n]
// Block: 128 rows x 16 cols, 256 threads, micro-tile 2x4. 64 blocks per matrix.
__device__ __forceinline__ void proj_body(const float* __restrict__ x,
                                          const float* __restrict__ W,
                                          const float* __restrict__ bias,
                                          const float* __restrict__ nz,
                                          float* __restrict__ out,
                                          int colBase)
{
    __shared__ float xs[32][132];   // [k][m], padded
    __shared__ float ws[32][16];    // [k][n]

    const int tid = threadIdx.x;          // 0..255
    const int tx  = tid & 3;              // 4 col-groups of 4
    const int ty  = tid >> 2;             // 64 row-groups of 2

    float acc[2][4];
#pragma unroll
    for (int i = 0; i < 2; i++)
#pragma unroll
        for (int j = 0; j < 4; j++) acc[i][j] = 0.f;

    for (int kk = 0; kk < DIM; kk += 32) {
        // x tile: 128 rows x 32 k = 1024 float4 / 256 threads = 4 each
#pragma unroll
        for (int r = 0; r < 4; r++) {
            int i  = tid + r * 256;
            int m  = i >> 3;
            int kq = (i & 7) << 2;
            float4 v = *reinterpret_cast<const float4*>(x + m * DIM + kk + kq);
            xs[kq + 0][m] = v.x;
            xs[kq + 1][m] = v.y;
            xs[kq + 2][m] = v.z;
            xs[kq + 3][m] = v.w;
        }
        // W tile: 32 k x 16 n = 128 float4; threads < 128
        if (tid < 128) {
            int k  = tid >> 2;
            int nq = (tid & 3) << 2;
            *reinterpret_cast<float4*>(&ws[k][nq]) =
                *reinterpret_cast<const float4*>(W + (kk + k) * DIM + colBase + nq);
        }
        __syncthreads();

#pragma unroll 8
        for (int k = 0; k < 32; k++) {
            float2 a = *reinterpret_cast<const float2*>(&xs[k][ty << 1]);
            float4 b = *reinterpret_cast<const float4*>(&ws[k][tx << 2]);
            acc[0][0] += a.x * b.x; acc[0][1] += a.x * b.y;
            acc[0][2] += a.x * b.z; acc[0][3] += a.x * b.w;
            acc[1][0] += a.y * b.x; acc[1][1] += a.y * b.y;
            acc[1][2] += a.y * b.z; acc[1][3] += a.y * b.w;
        }
        __syncthreads();
    }

    int n0 = colBase + (tx << 2);
    float4 bb = *reinterpret_cast<const float4*>(bias + n0);
#pragma unroll
    for (int i = 0; i < 2; i++) {
        int m = (ty << 1) + i;
        float4 nn = *reinterpret_cast<const float4*>(nz + m * DIM + n0);
        float4 r;
        r.x = acc[i][0] + bb.x + SIGMA * nn.x;
        r.y = acc[i][1] + bb.y + SIGMA * nn.y;
        r.z = acc[i][2] + bb.z + SIGMA * nn.z;
        r.w = acc[i][3] + bb.w + SIGMA * nn.w;
        *reinterpret_cast<float4*>(out + m * DIM + n0) = r;
    }
}

__global__ void __launch_bounds__(256)
proj3_kernel(const float* __restrict__ q, const float* __restrict__ k,
             const float* __restrict__ v,
             const float* __restrict__ Wq, const float* __restrict__ Wk,
             const float* __restrict__ Wv,
             const float* __restrict__ bq, const float* __restrict__ bk,
             const float* __restrict__ bv,
             const float* __restrict__ nq, const float* __restrict__ nk,
             const float* __restrict__ nv)
{
    int mat = blockIdx.y;
    const float* x = (mat == 0) ? q  : (mat == 1) ? k  : v;
    const float* W = (mat == 0) ? Wq : (mat == 1) ? Wk : Wv;
    const float* b = (mat == 0) ? bq : (mat == 1) ? bk : bv;
    const float* n = (mat == 0) ? nq : (mat == 1) ? nk : nv;
    float* o       = (mat == 0) ? g_qp : (mat == 1) ? g_kp : g_vp;
    proj_body(x, W, b, n, o, blockIdx.x * 16);
}

__global__ void __launch_bounds__(256)
projZ_kernel(const float* __restrict__ Wz, const float* __restrict__ bz,
             const float* __restrict__ nz, float* __restrict__ z_out)
{
    proj_body(g_zh, Wz, bz, nz, z_out, blockIdx.x * 16);
}

// ---------------- copy K -> K_out (with slot write) + logits ----------------
// (R1 form — verbatim: 81.4% DRAM measured; do not touch)
__global__ void __launch_bounds__(256)
copyK_kernel(const float* __restrict__ K, float* __restrict__ Kout,
             float* __restrict__ logits, const int* __restrict__ tptr)
{
    const int bp  = blockIdx.y;
    const int s0  = blockIdx.x * 32;
    const int tid = threadIdx.x;
    const int t   = *tptr;

    __shared__ float pds[32][256];   // per-s, per-thread partial dot

    float4 q4 = *reinterpret_cast<const float4*>(g_qp + bp * DIM + (tid << 2));
    const float* kprow = g_kp + bp * DIM;
    const float* Kb = K    + (size_t)bp * SEQ * DIM;
    float*       Ob = Kout + (size_t)bp * SEQ * DIM;

#pragma unroll 4
    for (int sl = 0; sl < 32; sl++) {
        int s = s0 + sl;
        const float* src = (s == t) ? kprow : (Kb + (size_t)s * DIM);
        float4 v = *reinterpret_cast<const float4*>(src + (tid << 2));
        *reinterpret_cast<float4*>(Ob + (size_t)s * DIM + (tid << 2)) = v;
        pds[sl][tid] = v.x * q4.x + v.y * q4.y + v.z * q4.z + v.w * q4.w;
    }
    __syncthreads();

    // 16 heads x 32 s = 512 reductions of 16 partials each
    for (int i = tid; i < 512; i += 256) {
        int h  = i & 15;
        int sl = i >> 4;
        float sum = 0.f;
#pragma unroll
        for (int j = 0; j < 16; j++) sum += pds[sl][(h << 4) + j];
        logits[((size_t)(bp * NH + h)) * SEQ + s0 + sl] = sum * SCALE;
    }
}

// ---------------- softmax in place over attn region (rows of 1024) ----------
__global__ void __launch_bounds__(256)
softmax_kernel(float* __restrict__ attn)
{
    int row  = blockIdx.x * 8 + (threadIdx.x >> 5);   // 2048 rows
    int lane = threadIdx.x & 31;
    float* p = attn + (size_t)row * SEQ;

    float v[32];
    float m = -1e30f;
#pragma unroll
    for (int i = 0; i < 32; i++) { v[i] = p[lane + (i << 5)]; m = fmaxf(m, v[i]); }
#pragma unroll
    for (int o = 16; o > 0; o >>= 1) m = fmaxf(m, __shfl_xor_sync(0xffffffffu, m, o));
    float sum = 0.f;
#pragma unroll
    for (int i = 0; i < 32; i++) { v[i] = __expf(v[i] - m); sum += v[i]; }
#pragma unroll
    for (int o = 16; o > 0; o >>= 1) sum += __shfl_xor_sync(0xffffffffu, sum, o);
    float inv = 1.f / sum;
#pragma unroll
    for (int i = 0; i < 32; i++) p[lane + (i << 5)] = v[i] * inv;
}

// ---------------- copy V -> V_out (slot write) + attn-weighted partials -----
// (R1 form — verbatim)
__global__ void __launch_bounds__(256)
copyV_kernel(const float* __restrict__ V, float* __restrict__ Vout,
             const float* __restrict__ attn, const int* __restrict__ tptr)
{
    const int bp  = blockIdx.y;
    const int s0  = blockIdx.x * 32;
    const int tid = threadIdx.x;
    const int t   = *tptr;

    __shared__ float as[NH][32];
    for (int i = tid; i < NH * 32; i += 256) {
        int h  = i >> 5;
        int sl = i & 31;
        as[h][sl] = attn[((size_t)(bp * NH + h)) * SEQ + s0 + sl];
    }
    __syncthreads();

    const float* vprow = g_vp + bp * DIM;
    const float* Vb = V    + (size_t)bp * SEQ * DIM;
    float*       Ob = Vout + (size_t)bp * SEQ * DIM;

    const int h = tid >> 4;   // head of cols 4t..4t+3
    float4 acc = make_float4(0.f, 0.f, 0.f, 0.f);

#pragma unroll 4
    for (int sl = 0; sl < 32; sl++) {
        int s = s0 + sl;
        const float* src = (s == t) ? vprow : (Vb + (size_t)s * DIM);
        float4 v = *reinterpret_cast<const float4*>(src + (tid << 2));
        *reinterpret_cast<float4*>(Ob + (size_t)s * DIM + (tid << 2)) = v;
        float a = as[h][sl];
        acc.x += a * v.x; acc.y += a * v.y; acc.z += a * v.z; acc.w += a * v.w;
    }
    *reinterpret_cast<float4*>(g_part + ((size_t)blockIdx.x * BP + bp) * DIM + (tid << 2)) = acc;
}

// ---------------- reduce the 32 s-chunk partials into g_zh ------------------
__global__ void __launch_bounds__(256)
reduce_kernel()
{
    int i = blockIdx.x * 256 + threadIdx.x;   // over BP*DIM = 131072
    float s = 0.f;
#pragma unroll
    for (int c = 0; c < 32; c++) s += g_part[c * (BP * DIM) + i];
    g_zh[i] = s;
}

// ---------------- launch ----------------------------------------------------
extern "C" void kernel_launch(void* const* d_in, const int* in_sizes, int n_in,
                              void* d_out, int out_size)
{
    const float* q   = (const float*)d_in[0];
    const float* k   = (const float*)d_in[1];
    const float* v   = (const float*)d_in[2];
    const float* Kin = (const float*)d_in[3];
    const float* Vin = (const float*)d_in[4];
    const float* Wq  = (const float*)d_in[5];
    const float* bq  = (const float*)d_in[6];
    const float* Wk  = (const float*)d_in[7];
    const float* bk  = (const float*)d_in[8];
    const float* Wv  = (const float*)d_in[9];
    const float* bv  = (const float*)d_in[10];
    const float* Wz  = (const float*)d_in[11];
    const float* bz  = (const float*)d_in[12];
    const float* nq  = (const float*)d_in[13];
    const float* nk  = (const float*)d_in[14];
    const float* nv  = (const float*)d_in[15];
    const float* nz  = (const float*)d_in[16];
    const int* tstep = (const int*)d_in[17];

    float* out   = (float*)d_out;
    float* z_out = out;                                       // 128*1024
    float* K_out = out + (size_t)BP * DIM;                    // 128*1024*1024
    float* V_out = K_out + (size_t)BP * SEQ * DIM;
    float* attn  = V_out + (size_t)BP * SEQ * DIM;            // 128*16*1024

    // 1. projections q/k/v (+bias +sigma*noise) — high-parallelism GEMM
    proj3_kernel<<<dim3(64, 3), 256>>>(q, k, v, Wq, Wk, Wv, bq, bk, bv, nq, nk, nv);
    // 2. K copy (slot write at t) fused with logits
    copyK_kernel<<<dim3(32, BP), 256>>>(Kin, K_out, attn, tstep);
    // 3. softmax in place
    softmax_kernel<<<256, 256>>>(attn);
    // 4. V copy (slot write at t) fused with attn-weighted partial sums
    copyV_kernel<<<dim3(32, BP), 256>>>(Vin, V_out, attn, tstep);
    // 5. reduce partials -> zh
    reduce_kernel<<<512, 256>>>();
    // 6. output projection z
    projZ_kernel<<<dim3(64, 1), 256>>>(Wz, bz, nz, z_out);
}